// round 1
// baseline (speedup 1.0000x reference)
#include <cuda_runtime.h>
#include <cuda_fp16.h>

#define N_NODES 32768
#define NPG     1024
#define HIDDEN  512
#define VBDIM   2048
#define VFDIM   512

// ---------------- scratch (device globals; no allocation allowed) ----------
__device__ __half g_vnb[(size_t)N_NODES * VBDIM];   // normalized body vis, fp16
__device__ __half g_vnf[(size_t)N_NODES * VFDIM];   // normalized face vis, fp16
__device__ float2 g_y[N_NODES];                     // attention output (rank-2)
__device__ float  g_score0[N_NODES];                // node score + root terms + consts
__device__ float  g_sb[N_NODES];                    // per-node body msg scalar
__device__ float  g_sf[N_NODES];                    // per-node face msg scalar
__device__ float  g_msgb[N_NODES], g_msgf[N_NODES];
__device__ float  g_degb[N_NODES], g_degf[N_NODES];
__device__ double g_stats[5];                       // S0,S1,S00,S01,S11 of y
__device__ float  g_M[4];                           // Wq @ Wk^T  (2x2)
__device__ float  g_u0[HIDDEN], g_ub[HIDDEN], g_uf[HIDDEN];
__device__ float  g_c[3];                           // const0, constb, constf

// ---------------- K1: tiny weight precompute (1 block, 512 threads) --------
__global__ void k1_precompute(
    const float* __restrict__ Wq,  const float* __restrict__ Wk,
    const float* __restrict__ Wm,  const float* __restrict__ bm,
    const float* __restrict__ Wnp, const float* __restrict__ bnp,
    const float* __restrict__ Wb_root, const float* __restrict__ Wb_msg, const float* __restrict__ bb,
    const float* __restrict__ Wf_root, const float* __restrict__ Wf_msg, const float* __restrict__ bf,
    const float* __restrict__ Wpb, const float* __restrict__ bpb,
    const float* __restrict__ Wpf, const float* __restrict__ bpf)
{
    __shared__ float red[512];
    __shared__ float w1c[32], wbm[32], wfm[32];
    const int t = threadIdx.x;

    // M[a][b] = sum_h Wq[a,h] * Wk[b,h]
    for (int a = 0; a < 2; a++) {
        for (int b = 0; b < 2; b++) {
            red[t] = Wq[a * HIDDEN + t] * Wk[b * HIDDEN + t];
            __syncthreads();
            for (int s = 256; s > 0; s >>= 1) {
                if (t < s) red[t] += red[t + s];
                __syncthreads();
            }
            if (t == 0) g_M[a * 2 + b] = red[0];
            __syncthreads();
        }
    }

    // 32-vectors: W1c = Wnp + Wb_root@Wpb + Wf_root@Wpf ; wbm = Wb_msg@Wpb ; wfm = Wf_msg@Wpf
    if (t < 32) {
        float vroot_b = 0.f, vroot_f = 0.f, vb = 0.f, vf = 0.f;
        for (int j = 0; j < 32; j++) {
            vroot_b += Wb_root[t * 32 + j] * Wpb[j];
            vroot_f += Wf_root[t * 32 + j] * Wpf[j];
            vb      += Wb_msg[t * 32 + j] * Wpb[j];
            vf      += Wf_msg[t * 32 + j] * Wpf[j];
        }
        w1c[t] = Wnp[t] + vroot_b + vroot_f;
        wbm[t] = vb;
        wfm[t] = vf;
    }
    __syncthreads();

    // 512-vectors: u* = Wm @ (32-vec)
    {
        float s0 = 0.f, sb = 0.f, sf = 0.f;
        for (int k = 0; k < 32; k++) {
            float wm = Wm[t * 32 + k];
            s0 = fmaf(wm, w1c[k], s0);
            sb = fmaf(wm, wbm[k], sb);
            sf = fmaf(wm, wfm[k], sf);
        }
        g_u0[t] = s0; g_ub[t] = sb; g_uf[t] = sf;
    }

    if (t == 0) {
        float c0 = bnp[0] + bpb[0] + bpf[0];
        float cb = 0.f, cf = 0.f;
        for (int k = 0; k < 32; k++) {
            c0 += bm[k] * w1c[k] + bb[k] * Wpb[k] + bf[k] * Wpf[k];
            cb += bm[k] * wbm[k];
            cf += bm[k] * wfm[k];
        }
        g_c[0] = c0; g_c[1] = cb; g_c[2] = cf;
    }
    if (t < 5) g_stats[t] = 0.0;
}

// ---------------- K2: rank-2 attention, 4 blocks per graph -----------------
__global__ void k2_attn(const float* __restrict__ x)
{
    __shared__ float2 xs[NPG];
    __shared__ double wsum[8][5];
    const int g = blockIdx.x >> 2;   // graph id
    const int q = blockIdx.x & 3;    // row quarter
    const int t = threadIdx.x;       // 256 threads
    const float* xg = x + (size_t)g * NPG * 2;

    for (int j = t; j < NPG; j += 256)
        xs[j] = make_float2(xg[2 * j], xg[2 * j + 1]);
    __syncthreads();

    const int i = q * 256 + t;
    const float2 xi = xs[i];
    const float inv = rsqrtf((float)HIDDEN);
    const float M00 = g_M[0], M01 = g_M[1], M10 = g_M[2], M11 = g_M[3];
    const float u0 = (xi.x * M00 + xi.y * M10) * inv;
    const float u1 = (xi.x * M01 + xi.y * M11) * inv;

    float m = -1e30f;
    for (int j = 0; j < NPG; j++) {
        float2 xj = xs[j];
        m = fmaxf(m, fmaf(u0, xj.x, u1 * xj.y));
    }
    float l = 0.f, a0 = 0.f, a1 = 0.f;
    for (int j = 0; j < NPG; j++) {
        float2 xj = xs[j];
        float s = fmaf(u0, xj.x, u1 * xj.y);
        float p = __expf(s - m);
        l += p; a0 = fmaf(p, xj.x, a0); a1 = fmaf(p, xj.y, a1);
    }
    const float y0 = a0 / l, y1 = a1 / l;
    g_y[g * NPG + i] = make_float2(y0, y1);

    // accumulate BN stats (5 sums) in double
    float v[5] = {y0, y1, y0 * y0, y0 * y1, y1 * y1};
    const int lane = t & 31, wrp = t >> 5;
    #pragma unroll
    for (int k = 0; k < 5; k++) {
        float s = v[k];
        for (int off = 16; off; off >>= 1) s += __shfl_down_sync(0xffffffffu, s, off);
        if (lane == 0) wsum[wrp][k] = (double)s;
    }
    __syncthreads();
    if (t == 0) {
        #pragma unroll
        for (int k = 0; k < 5; k++) {
            double s = 0.0;
            for (int w = 0; w < 8; w++) s += wsum[w][k];
            atomicAdd(&g_stats[k], s);
        }
    }
}

// ---------------- K3: normalize visual features to fp16 --------------------
__global__ void k3_norm_body(const float* __restrict__ vis)
{
    __shared__ float sred[256];
    const int n = blockIdx.x, t = threadIdx.x; // 256 threads, 2048 floats/row
    const float4* row = (const float4*)(vis + (size_t)n * VBDIM); // 512 float4
    float4 a = row[t], b = row[t + 256];
    float ss = a.x*a.x + a.y*a.y + a.z*a.z + a.w*a.w
             + b.x*b.x + b.y*b.y + b.z*b.z + b.w*b.w;
    sred[t] = ss; __syncthreads();
    for (int s = 128; s > 0; s >>= 1) {
        if (t < s) sred[t] += sred[t + s];
        __syncthreads();
    }
    const float r = rsqrtf(sred[0] + 1e-8f);
    half2* o2 = (half2*)(g_vnb + (size_t)n * VBDIM);
    o2[2 * t]             = __floats2half2_rn(a.x * r, a.y * r);
    o2[2 * t + 1]         = __floats2half2_rn(a.z * r, a.w * r);
    o2[2 * (t + 256)]     = __floats2half2_rn(b.x * r, b.y * r);
    o2[2 * (t + 256) + 1] = __floats2half2_rn(b.z * r, b.w * r);
}

__global__ void k3_norm_face(const float* __restrict__ vis)
{
    __shared__ float sred[128];
    const int n = blockIdx.x, t = threadIdx.x; // 128 threads, 512 floats/row
    const float4* row = (const float4*)(vis + (size_t)n * VFDIM); // 128 float4
    float4 a = row[t];
    float ss = a.x*a.x + a.y*a.y + a.z*a.z + a.w*a.w;
    sred[t] = ss; __syncthreads();
    for (int s = 64; s > 0; s >>= 1) {
        if (t < s) sred[t] += sred[t + s];
        __syncthreads();
    }
    const float r = rsqrtf(sred[0] + 1e-8f);
    half2* o2 = (half2*)(g_vnf + (size_t)n * VFDIM);
    o2[2 * t]     = __floats2half2_rn(a.x * r, a.y * r);
    o2[2 * t + 1] = __floats2half2_rn(a.z * r, a.w * r);
}

// ---------------- K4: per-node BN + PReLU + 3 scalar projections -----------
__global__ void k4_node(const float* __restrict__ Wv,
                        const float* __restrict__ gamma,
                        const float* __restrict__ beta,
                        const float* __restrict__ prelu_a)
{
    __shared__ float A0[HIDDEN], A1[HIDDEN], D[HIDDEN];
    __shared__ float U0[HIDDEN], UB[HIDDEN], UF[HIDDEN];
    const int t = threadIdx.x; // 256

    const double invN = 1.0 / (double)N_NODES;
    const double m0 = g_stats[0] * invN, m1 = g_stats[1] * invN;
    const double C00 = g_stats[2] * invN - m0 * m0;
    const double C01 = g_stats[3] * invN - m0 * m1;
    const double C11 = g_stats[4] * invN - m1 * m1;

    for (int h = t; h < HIDDEN; h += 256) {
        const float w0 = Wv[h], w1 = Wv[HIDDEN + h];
        const float var = (float)((double)w0 * w0 * C00 + 2.0 * w0 * w1 * C01 + (double)w1 * w1 * C11);
        const float mu  = (float)((double)w0 * m0 + (double)w1 * m1);
        const float gg  = gamma[h] * rsqrtf(var + 1e-5f);
        A0[h] = w0 * gg;
        A1[h] = w1 * gg;
        D[h]  = beta[h] - mu * gg;
        U0[h] = g_u0[h]; UB[h] = g_ub[h]; UF[h] = g_uf[h];
    }
    __syncthreads();

    const int n = blockIdx.x * 256 + t;
    const float2 y = g_y[n];
    const float aa = prelu_a[0];
    float acc0 = 0.f, accb = 0.f, accf = 0.f;
    #pragma unroll 8
    for (int h = 0; h < HIDDEN; h++) {
        float v = fmaf(A0[h], y.x, fmaf(A1[h], y.y, D[h]));
        v = (v >= 0.f) ? v : aa * v;
        acc0 = fmaf(v, U0[h], acc0);
        accb = fmaf(v, UB[h], accb);
        accf = fmaf(v, UF[h], accf);
    }
    g_score0[n] = acc0 + g_c[0];
    g_sb[n]     = accb + g_c[1];
    g_sf[n]     = accf + g_c[2];
    g_msgb[n] = 0.f; g_msgf[n] = 0.f; g_degb[n] = 0.f; g_degf[n] = 0.f;
}

// ---------------- K5: edge cosine weights + scalar scatter -----------------
// One warp per edge (grid-stride). ITERS uint4-chunks of 32 lanes each per row.
template<int ITERS, bool BODY>
__global__ void k5_edges(const int* __restrict__ edges, int E)
{
    const __half* __restrict__ vn = BODY ? g_vnb : g_vnf;
    const float*  __restrict__ s  = BODY ? g_sb  : g_sf;
    float* __restrict__ msg = BODY ? g_msgb : g_msgf;
    float* __restrict__ deg = BODY ? g_degb : g_degf;
    const int rowu4 = ITERS * 32;

    const int lane = threadIdx.x & 31;
    const int nwarps = (gridDim.x * blockDim.x) >> 5;
    int w = (blockIdx.x * blockDim.x + threadIdx.x) >> 5;

    for (int e = w; e < E; e += nwarps) {
        const int src = edges[e];
        const int dst = edges[E + e];
        const uint4* ps = (const uint4*)vn + (size_t)src * rowu4 + lane;
        const uint4* pd = (const uint4*)vn + (size_t)dst * rowu4 + lane;
        float acc = 0.f;
        #pragma unroll
        for (int c = 0; c < ITERS; c++) {
            uint4 a = ps[c * 32];
            uint4 b = pd[c * 32];
            const half2* ha = (const half2*)&a;
            const half2* hb = (const half2*)&b;
            #pragma unroll
            for (int k = 0; k < 4; k++) {
                float2 fa = __half22float2(ha[k]);
                float2 fb = __half22float2(hb[k]);
                acc = fmaf(fa.x, fb.x, acc);
                acc = fmaf(fa.y, fb.y, acc);
            }
        }
        for (int off = 16; off; off >>= 1) acc += __shfl_down_sync(0xffffffffu, acc, off);
        if (lane == 0) {
            atomicAdd(&msg[dst], acc * __ldg(&s[src]));
            atomicAdd(&deg[dst], 1.0f);
        }
    }
}

// ---------------- K6: final combine ----------------------------------------
__global__ void k6_final(float* __restrict__ out)
{
    const int n = blockIdx.x * 256 + threadIdx.x;
    out[n] = g_score0[n]
           + g_msgb[n] / fmaxf(g_degb[n], 1.0f)
           + g_msgf[n] / fmaxf(g_degf[n], 1.0f);
}

// ---------------- launch ----------------------------------------------------
extern "C" void kernel_launch(void* const* d_in, const int* in_sizes, int n_in,
                              void* d_out, int out_size)
{
    const float* x        = (const float*)d_in[0];
    const float* vis_body = (const float*)d_in[1];
    const float* vis_face = (const float*)d_in[2];
    const int*   edge_b   = (const int*)d_in[3];
    const int*   edge_f   = (const int*)d_in[4];
    const int E = in_sizes[3] / 2;

    // batch_size may or may not be materialized as an input; detect via size
    int base = 5;
    if (n_in > 5 && in_sizes[5] == 1) base = 6;   // skip batch_size scalar
    const float* Wq      = (const float*)d_in[base + 0];
    const float* Wk      = (const float*)d_in[base + 1];
    const float* Wv      = (const float*)d_in[base + 2];
    const float* gamma   = (const float*)d_in[base + 3];
    const float* beta    = (const float*)d_in[base + 4];
    const float* prelu_a = (const float*)d_in[base + 5];
    const float* Wm      = (const float*)d_in[base + 6];
    const float* bm      = (const float*)d_in[base + 7];
    const float* Wnp     = (const float*)d_in[base + 8];
    const float* bnp     = (const float*)d_in[base + 9];
    const float* Wb_root = (const float*)d_in[base + 10];
    const float* Wb_msg  = (const float*)d_in[base + 11];
    const float* bb      = (const float*)d_in[base + 12];
    const float* Wf_root = (const float*)d_in[base + 13];
    const float* Wf_msg  = (const float*)d_in[base + 14];
    const float* bf      = (const float*)d_in[base + 15];
    const float* Wpb     = (const float*)d_in[base + 16];
    const float* bpb     = (const float*)d_in[base + 17];
    const float* Wpf     = (const float*)d_in[base + 18];
    const float* bpf     = (const float*)d_in[base + 19];

    k1_precompute<<<1, 512>>>(Wq, Wk, Wm, bm, Wnp, bnp,
                              Wb_root, Wb_msg, bb, Wf_root, Wf_msg, bf,
                              Wpb, bpb, Wpf, bpf);
    k2_attn<<<128, 256>>>(x);
    k3_norm_body<<<N_NODES, 256>>>(vis_body);
    k3_norm_face<<<N_NODES, 128>>>(vis_face);
    k4_node<<<N_NODES / 256, 256>>>(Wv, gamma, beta, prelu_a);
    k5_edges<VBDIM / 256, true><<<8192, 256>>>(edge_b, E);
    k5_edges<VFDIM / 256, false><<<4096, 256>>>(edge_f, E);
    k6_final<<<N_NODES / 256, 256>>>((float*)d_out);
}

// round 3
// speedup vs baseline: 2.1570x; 2.1570x over previous
#include <cuda_runtime.h>
#include <cuda_fp16.h>
#include <cstdint>
#include <cstddef>

#define N_NODES 32768
#define NPG     1024
#define HIDDEN  512
#define VBDIM   2048
#define VFDIM   512
#define EDGES   (N_NODES * 32)

// ---------------- scratch (device globals; no allocation allowed) ----------
__device__ int4   g_qb[(size_t)N_NODES * VBDIM / 16];  // int8 quantized body rows
__device__ int4   g_qf[(size_t)N_NODES * VFDIM / 16];  // int8 quantized face rows
__device__ float  g_scb[N_NODES], g_scf[N_NODES];      // per-row dequant scale (incl. L2 norm)
__device__ float2 g_y[N_NODES];                        // attention output (rank-2)
__device__ float  g_score0[N_NODES];
__device__ float  g_ssb[N_NODES], g_ssf[N_NODES];      // scale_src * s_src, premultiplied
__device__ float  g_msgb[N_NODES], g_msgf[N_NODES];
__device__ double g_stats[5];
__device__ float  g_M[4];
__device__ float  g_u0[HIDDEN], g_ub[HIDDEN], g_uf[HIDDEN];
__device__ float  g_c[3];
// edge sorting
__device__ int g_cntb[N_NODES], g_cntf[N_NODES];
__device__ int g_offb[N_NODES + 1], g_offf[N_NODES + 1];
__device__ int g_curb[N_NODES], g_curf[N_NODES];
__device__ int g_esb[EDGES], g_esf[EDGES];

// ---------------- K1: tiny weight precompute (1 block, 512 threads) --------
__global__ void k1_precompute(
    const float* __restrict__ Wq,  const float* __restrict__ Wk,
    const float* __restrict__ Wm,  const float* __restrict__ bm,
    const float* __restrict__ Wnp, const float* __restrict__ bnp,
    const float* __restrict__ Wb_root, const float* __restrict__ Wb_msg, const float* __restrict__ bb,
    const float* __restrict__ Wf_root, const float* __restrict__ Wf_msg, const float* __restrict__ bf,
    const float* __restrict__ Wpb, const float* __restrict__ bpb,
    const float* __restrict__ Wpf, const float* __restrict__ bpf)
{
    __shared__ float red[512];
    __shared__ float w1c[32], wbm[32], wfm[32];
    const int t = threadIdx.x;

    for (int a = 0; a < 2; a++) {
        for (int b = 0; b < 2; b++) {
            red[t] = Wq[a * HIDDEN + t] * Wk[b * HIDDEN + t];
            __syncthreads();
            for (int s = 256; s > 0; s >>= 1) {
                if (t < s) red[t] += red[t + s];
                __syncthreads();
            }
            if (t == 0) g_M[a * 2 + b] = red[0];
            __syncthreads();
        }
    }

    if (t < 32) {
        float vroot_b = 0.f, vroot_f = 0.f, vb = 0.f, vf = 0.f;
        for (int j = 0; j < 32; j++) {
            vroot_b += Wb_root[t * 32 + j] * Wpb[j];
            vroot_f += Wf_root[t * 32 + j] * Wpf[j];
            vb      += Wb_msg[t * 32 + j] * Wpb[j];
            vf      += Wf_msg[t * 32 + j] * Wpf[j];
        }
        w1c[t] = Wnp[t] + vroot_b + vroot_f;
        wbm[t] = vb;
        wfm[t] = vf;
    }
    __syncthreads();

    {
        float s0 = 0.f, sb = 0.f, sf = 0.f;
        for (int k = 0; k < 32; k++) {
            float wm = Wm[t * 32 + k];
            s0 = fmaf(wm, w1c[k], s0);
            sb = fmaf(wm, wbm[k], sb);
            sf = fmaf(wm, wfm[k], sf);
        }
        g_u0[t] = s0; g_ub[t] = sb; g_uf[t] = sf;
    }

    if (t == 0) {
        float c0 = bnp[0] + bpb[0] + bpf[0];
        float cb = 0.f, cf = 0.f;
        for (int k = 0; k < 32; k++) {
            c0 += bm[k] * w1c[k] + bb[k] * Wpb[k] + bf[k] * Wpf[k];
            cb += bm[k] * wbm[k];
            cf += bm[k] * wfm[k];
        }
        g_c[0] = c0; g_c[1] = cb; g_c[2] = cf;
    }
    if (t < 5) g_stats[t] = 0.0;
}

// ---------------- K2: rank-2 attention, 4 blocks per graph -----------------
__global__ void k2_attn(const float* __restrict__ x)
{
    __shared__ float2 xs[NPG];
    __shared__ double wsum[8][5];
    const int g = blockIdx.x >> 2;
    const int q = blockIdx.x & 3;
    const int t = threadIdx.x;
    const float* xg = x + (size_t)g * NPG * 2;

    for (int j = t; j < NPG; j += 256)
        xs[j] = make_float2(xg[2 * j], xg[2 * j + 1]);
    __syncthreads();

    const int i = q * 256 + t;
    const float2 xi = xs[i];
    const float inv = rsqrtf((float)HIDDEN);
    const float M00 = g_M[0], M01 = g_M[1], M10 = g_M[2], M11 = g_M[3];
    const float u0 = (xi.x * M00 + xi.y * M10) * inv;
    const float u1 = (xi.x * M01 + xi.y * M11) * inv;

    float m = -1e30f;
    for (int j = 0; j < NPG; j++) {
        float2 xj = xs[j];
        m = fmaxf(m, fmaf(u0, xj.x, u1 * xj.y));
    }
    float l = 0.f, a0 = 0.f, a1 = 0.f;
    for (int j = 0; j < NPG; j++) {
        float2 xj = xs[j];
        float s = fmaf(u0, xj.x, u1 * xj.y);
        float p = __expf(s - m);
        l += p; a0 = fmaf(p, xj.x, a0); a1 = fmaf(p, xj.y, a1);
    }
    const float y0 = a0 / l, y1 = a1 / l;
    g_y[g * NPG + i] = make_float2(y0, y1);

    float v[5] = {y0, y1, y0 * y0, y0 * y1, y1 * y1};
    const int lane = t & 31, wrp = t >> 5;
    #pragma unroll
    for (int k = 0; k < 5; k++) {
        float s = v[k];
        for (int off = 16; off; off >>= 1) s += __shfl_down_sync(0xffffffffu, s, off);
        if (lane == 0) wsum[wrp][k] = (double)s;
    }
    __syncthreads();
    if (t == 0) {
        #pragma unroll
        for (int k = 0; k < 5; k++) {
            double s = 0.0;
            for (int w = 0; w < 8; w++) s += wsum[w][k];
            atomicAdd(&g_stats[k], s);
        }
    }
}

// ---------------- K3: normalize + int8 quantize visual features ------------
__device__ __forceinline__ unsigned int pack4(float4 a, float qs)
{
    int x = __float2int_rn(a.x * qs);
    int y = __float2int_rn(a.y * qs);
    int z = __float2int_rn(a.z * qs);
    int w = __float2int_rn(a.w * qs);
    return (unsigned int)((x & 0xFF) | ((y & 0xFF) << 8) | ((z & 0xFF) << 16) | ((w & 0xFF) << 24));
}

__global__ void k3_norm_body(const float* __restrict__ vis)
{
    __shared__ float s_s[8], s_m[8];
    const int n = blockIdx.x, t = threadIdx.x; // 256 threads
    const int lane = t & 31, wrp = t >> 5;
    const float4* row = (const float4*)(vis + (size_t)n * VBDIM);
    float4 a = row[t], b = row[t + 256];
    float ss = a.x*a.x + a.y*a.y + a.z*a.z + a.w*a.w
             + b.x*b.x + b.y*b.y + b.z*b.z + b.w*b.w;
    float mx = fmaxf(fmaxf(fmaxf(fabsf(a.x), fabsf(a.y)), fmaxf(fabsf(a.z), fabsf(a.w))),
                     fmaxf(fmaxf(fabsf(b.x), fabsf(b.y)), fmaxf(fabsf(b.z), fabsf(b.w))));
    for (int o = 16; o; o >>= 1) {
        ss += __shfl_down_sync(0xffffffffu, ss, o);
        mx = fmaxf(mx, __shfl_down_sync(0xffffffffu, mx, o));
    }
    if (lane == 0) { s_s[wrp] = ss; s_m[wrp] = mx; }
    __syncthreads();
    if (t == 0) {
        float ts = 0.f, tm = 0.f;
        #pragma unroll
        for (int w = 0; w < 8; w++) { ts += s_s[w]; tm = fmaxf(tm, s_m[w]); }
        s_s[0] = ts; s_m[0] = fmaxf(tm, 1e-20f);
    }
    __syncthreads();
    const float mxa = s_m[0];
    const float qs = 127.f / mxa;
    unsigned int* o = (unsigned int*)(g_qb + (size_t)n * (VBDIM / 16));
    o[t]       = pack4(a, qs);
    o[t + 256] = pack4(b, qs);
    if (t == 0) g_scb[n] = mxa * rsqrtf(s_s[0] + 1e-8f) * (1.f / 127.f);
}

__global__ void k3_norm_face(const float* __restrict__ vis)
{
    __shared__ float s_s[4], s_m[4];
    const int n = blockIdx.x, t = threadIdx.x; // 128 threads
    const int lane = t & 31, wrp = t >> 5;
    const float4* row = (const float4*)(vis + (size_t)n * VFDIM);
    float4 a = row[t];
    float ss = a.x*a.x + a.y*a.y + a.z*a.z + a.w*a.w;
    float mx = fmaxf(fmaxf(fabsf(a.x), fabsf(a.y)), fmaxf(fabsf(a.z), fabsf(a.w)));
    for (int o = 16; o; o >>= 1) {
        ss += __shfl_down_sync(0xffffffffu, ss, o);
        mx = fmaxf(mx, __shfl_down_sync(0xffffffffu, mx, o));
    }
    if (lane == 0) { s_s[wrp] = ss; s_m[wrp] = mx; }
    __syncthreads();
    if (t == 0) {
        float ts = 0.f, tm = 0.f;
        #pragma unroll
        for (int w = 0; w < 4; w++) { ts += s_s[w]; tm = fmaxf(tm, s_m[w]); }
        s_s[0] = ts; s_m[0] = fmaxf(tm, 1e-20f);
    }
    __syncthreads();
    const float mxa = s_m[0];
    const float qs = 127.f / mxa;
    unsigned int* o = (unsigned int*)(g_qf + (size_t)n * (VFDIM / 16));
    o[t] = pack4(a, qs);
    if (t == 0) g_scf[n] = mxa * rsqrtf(s_s[0] + 1e-8f) * (1.f / 127.f);
}

// ---------------- edge counting sort ----------------------------------------
__global__ void k_zero()
{
    const int n = blockIdx.x * 256 + threadIdx.x;
    if (n < N_NODES) { g_cntb[n] = 0; g_cntf[n] = 0; }
}

__global__ void k_hist(const int* __restrict__ eb, const int* __restrict__ ef, int E)
{
    const int e = blockIdx.x * 256 + threadIdx.x;
    if (e < E) {
        atomicAdd(&g_cntb[eb[E + e]], 1);
        atomicAdd(&g_cntf[ef[E + e]], 1);
    }
}

__global__ void k_scan()   // <<<2, 1024>>> : block 0 = body, block 1 = face
{
    __shared__ int part[1024];
    const int t = threadIdx.x;
    int* cnt = blockIdx.x ? g_cntf : g_cntb;
    int* off = blockIdx.x ? g_offf : g_offb;
    int* cur = blockIdx.x ? g_curf : g_curb;
    const int base = t * 32;
    int local[32];
    int s = 0;
    #pragma unroll
    for (int i = 0; i < 32; i++) { local[i] = cnt[base + i]; s += local[i]; }
    part[t] = s;
    __syncthreads();
    for (int d = 1; d < 1024; d <<= 1) {
        int v = (t >= d) ? part[t - d] : 0;
        __syncthreads();
        part[t] += v;
        __syncthreads();
    }
    int run = (t > 0) ? part[t - 1] : 0;
    #pragma unroll
    for (int i = 0; i < 32; i++) {
        off[base + i] = run;
        cur[base + i] = run;
        run += local[i];
    }
    if (t == 1023) off[N_NODES] = run;
}

__global__ void k_scatter(const int* __restrict__ eb, const int* __restrict__ ef, int E)
{
    const int e = blockIdx.x * 256 + threadIdx.x;
    if (e < E) {
        int sb = eb[e], db = eb[E + e];
        g_esb[atomicAdd(&g_curb[db], 1)] = sb;
        int sf = ef[e], df = ef[E + e];
        g_esf[atomicAdd(&g_curf[df], 1)] = sf;
    }
}

// ---------------- K4: per-node BN + PReLU + 3 scalar projections -----------
__global__ void k4_node(const float* __restrict__ Wv,
                        const float* __restrict__ gamma,
                        const float* __restrict__ beta,
                        const float* __restrict__ prelu_a)
{
    __shared__ float A0[HIDDEN], A1[HIDDEN], D[HIDDEN];
    __shared__ float U0[HIDDEN], UB[HIDDEN], UF[HIDDEN];
    const int t = threadIdx.x; // 256

    const double invN = 1.0 / (double)N_NODES;
    const double m0 = g_stats[0] * invN, m1 = g_stats[1] * invN;
    const double C00 = g_stats[2] * invN - m0 * m0;
    const double C01 = g_stats[3] * invN - m0 * m1;
    const double C11 = g_stats[4] * invN - m1 * m1;

    for (int h = t; h < HIDDEN; h += 256) {
        const float w0 = Wv[h], w1 = Wv[HIDDEN + h];
        const float var = (float)((double)w0 * w0 * C00 + 2.0 * w0 * w1 * C01 + (double)w1 * w1 * C11);
        const float mu  = (float)((double)w0 * m0 + (double)w1 * m1);
        const float gg  = gamma[h] * rsqrtf(var + 1e-5f);
        A0[h] = w0 * gg;
        A1[h] = w1 * gg;
        D[h]  = beta[h] - mu * gg;
        U0[h] = g_u0[h]; UB[h] = g_ub[h]; UF[h] = g_uf[h];
    }
    __syncthreads();

    const int n = blockIdx.x * 256 + t;
    const float2 y = g_y[n];
    const float aa = prelu_a[0];
    float acc0 = 0.f, accb = 0.f, accf = 0.f;
    #pragma unroll 8
    for (int h = 0; h < HIDDEN; h++) {
        float v = fmaf(A0[h], y.x, fmaf(A1[h], y.y, D[h]));
        v = (v >= 0.f) ? v : aa * v;
        acc0 = fmaf(v, U0[h], acc0);
        accb = fmaf(v, UB[h], accb);
        accf = fmaf(v, UF[h], accf);
    }
    g_score0[n] = acc0 + g_c[0];
    g_ssb[n]    = (accb + g_c[1]) * g_scb[n];   // fold src dequant scale into s
    g_ssf[n]    = (accf + g_c[2]) * g_scf[n];
}

// ---------------- K5: dst-grouped int8 cosine message passing --------------
// One warp per dst node. dst row cached in registers; src rows gathered.
template<int ROWI4, bool BODY>   // ROWI4 = int4 per row (128 body / 32 face)
__global__ void k5_sorted()
{
    const int wid = (blockIdx.x * blockDim.x + threadIdx.x) >> 5;
    const int lane = threadIdx.x & 31;
    if (wid >= N_NODES) return;

    const int4*  __restrict__ q      = BODY ? g_qb  : g_qf;
    const int*   __restrict__ off    = BODY ? g_offb : g_offf;
    const int*   __restrict__ sorted = BODY ? g_esb : g_esf;
    const float* __restrict__ ss     = BODY ? g_ssb : g_ssf;
    const float* __restrict__ sc     = BODY ? g_scb : g_scf;
    float*       __restrict__ msg    = BODY ? g_msgb : g_msgf;

    constexpr int C = ROWI4 / 32;   // int4 chunks per lane
    int4 dreg[C];
    #pragma unroll
    for (int c = 0; c < C; c++)
        dreg[c] = q[(size_t)wid * ROWI4 + c * 32 + lane];

    const int start = off[wid], end = off[wid + 1];
    float fl = 0.f;
    for (int e = start; e < end; e++) {
        const int src = sorted[e];
        const int4* ps = q + (size_t)src * ROWI4 + lane;
        int id = 0;
        #pragma unroll
        for (int c = 0; c < C; c++) {
            int4 s4 = ps[c * 32];
            id = __dp4a(s4.x, dreg[c].x, id);
            id = __dp4a(s4.y, dreg[c].y, id);
            id = __dp4a(s4.z, dreg[c].z, id);
            id = __dp4a(s4.w, dreg[c].w, id);
        }
        fl = fmaf((float)id, __ldg(&ss[src]), fl);
    }
    for (int o = 16; o; o >>= 1) fl += __shfl_down_sync(0xffffffffu, fl, o);
    if (lane == 0) msg[wid] = fl * sc[wid];
}

// ---------------- K6: final combine ----------------------------------------
__global__ void k6_final(float* __restrict__ out)
{
    const int n = blockIdx.x * 256 + threadIdx.x;
    const float db = (float)(g_offb[n + 1] - g_offb[n]);
    const float df = (float)(g_offf[n + 1] - g_offf[n]);
    out[n] = g_score0[n]
           + g_msgb[n] / fmaxf(db, 1.0f)
           + g_msgf[n] / fmaxf(df, 1.0f);
}

// ---------------- launch ----------------------------------------------------
extern "C" void kernel_launch(void* const* d_in, const int* in_sizes, int n_in,
                              void* d_out, int out_size)
{
    const float* x        = (const float*)d_in[0];
    const float* vis_body = (const float*)d_in[1];
    const float* vis_face = (const float*)d_in[2];
    const int*   edge_b   = (const int*)d_in[3];
    const int*   edge_f   = (const int*)d_in[4];
    const int E = in_sizes[3] / 2;

    int base = 5;
    if (n_in > 5 && in_sizes[5] == 1) base = 6;
    const float* Wq      = (const float*)d_in[base + 0];
    const float* Wk      = (const float*)d_in[base + 1];
    const float* Wv      = (const float*)d_in[base + 2];
    const float* gamma   = (const float*)d_in[base + 3];
    const float* beta    = (const float*)d_in[base + 4];
    const float* prelu_a = (const float*)d_in[base + 5];
    const float* Wm      = (const float*)d_in[base + 6];
    const float* bm      = (const float*)d_in[base + 7];
    const float* Wnp     = (const float*)d_in[base + 8];
    const float* bnp     = (const float*)d_in[base + 9];
    const float* Wb_root = (const float*)d_in[base + 10];
    const float* Wb_msg  = (const float*)d_in[base + 11];
    const float* bb      = (const float*)d_in[base + 12];
    const float* Wf_root = (const float*)d_in[base + 13];
    const float* Wf_msg  = (const float*)d_in[base + 14];
    const float* bf      = (const float*)d_in[base + 15];
    const float* Wpb     = (const float*)d_in[base + 16];
    const float* bpb     = (const float*)d_in[base + 17];
    const float* Wpf     = (const float*)d_in[base + 18];
    const float* bpf     = (const float*)d_in[base + 19];

    k1_precompute<<<1, 512>>>(Wq, Wk, Wm, bm, Wnp, bnp,
                              Wb_root, Wb_msg, bb, Wf_root, Wf_msg, bf,
                              Wpb, bpb, Wpf, bpf);
    k2_attn<<<128, 256>>>(x);
    k3_norm_body<<<N_NODES, 256>>>(vis_body);
    k3_norm_face<<<N_NODES, 128>>>(vis_face);

    k_zero<<<N_NODES / 256, 256>>>();
    k_hist<<<(E + 255) / 256, 256>>>(edge_b, edge_f, E);
    k_scan<<<2, 1024>>>();
    k_scatter<<<(E + 255) / 256, 256>>>(edge_b, edge_f, E);

    k4_node<<<N_NODES / 256, 256>>>(Wv, gamma, beta, prelu_a);

    k5_sorted<VBDIM / 16, true ><<<N_NODES / 8, 256>>>();
    k5_sorted<VFDIM / 16, false><<<N_NODES / 8, 256>>>();

    k6_final<<<N_NODES / 256, 256>>>((float*)d_out);
}

// round 5
// speedup vs baseline: 2.1839x; 1.0124x over previous
#include <cuda_runtime.h>
#include <cuda_fp16.h>
#include <cstdint>
#include <cstddef>

#define N_NODES 32768
#define NPG     1024
#define HIDDEN  512
#define VBDIM   2048
#define VFDIM   512
#define EDGES   (N_NODES * 32)

// ---------------- scratch (device globals; no allocation allowed) ----------
__device__ int4   g_qb[(size_t)N_NODES * VBDIM / 16];  // int8 quantized body rows
__device__ int4   g_qf[(size_t)N_NODES * VFDIM / 16];  // int8 quantized face rows
__device__ float  g_scb[N_NODES], g_scf[N_NODES];      // per-row dequant scale (incl. L2 norm)
__device__ float2 g_y[N_NODES];                        // attention output (rank-2)
__device__ float  g_score0[N_NODES];
__device__ float  g_ssb[N_NODES], g_ssf[N_NODES];      // scale_src * s_src, premultiplied
__device__ float  g_msgb[N_NODES], g_msgf[N_NODES];
__device__ double g_stats[5];
__device__ float  g_M[4];
__device__ float  g_u0[HIDDEN], g_ub[HIDDEN], g_uf[HIDDEN];
__device__ float  g_c[3];
// edge sorting
__device__ int g_cntb[N_NODES], g_cntf[N_NODES];
__device__ int g_offb[N_NODES + 1], g_offf[N_NODES + 1];
__device__ int g_curb[N_NODES], g_curf[N_NODES];
__device__ int g_esb[EDGES], g_esf[EDGES];

// ---------------- K1: tiny weight precompute (1 block, 512 threads) --------
__global__ void k1_precompute(
    const float* __restrict__ Wq,  const float* __restrict__ Wk,
    const float* __restrict__ Wm,  const float* __restrict__ bm,
    const float* __restrict__ Wnp, const float* __restrict__ bnp,
    const float* __restrict__ Wb_root, const float* __restrict__ Wb_msg, const float* __restrict__ bb,
    const float* __restrict__ Wf_root, const float* __restrict__ Wf_msg, const float* __restrict__ bf,
    const float* __restrict__ Wpb, const float* __restrict__ bpb,
    const float* __restrict__ Wpf, const float* __restrict__ bpf)
{
    __shared__ float red[512];
    __shared__ float w1c[32], wbm[32], wfm[32];
    const int t = threadIdx.x;

    for (int a = 0; a < 2; a++) {
        for (int b = 0; b < 2; b++) {
            red[t] = Wq[a * HIDDEN + t] * Wk[b * HIDDEN + t];
            __syncthreads();
            for (int s = 256; s > 0; s >>= 1) {
                if (t < s) red[t] += red[t + s];
                __syncthreads();
            }
            if (t == 0) g_M[a * 2 + b] = red[0];
            __syncthreads();
        }
    }

    if (t < 32) {
        float vroot_b = 0.f, vroot_f = 0.f, vb = 0.f, vf = 0.f;
        for (int j = 0; j < 32; j++) {
            vroot_b += Wb_root[t * 32 + j] * Wpb[j];
            vroot_f += Wf_root[t * 32 + j] * Wpf[j];
            vb      += Wb_msg[t * 32 + j] * Wpb[j];
            vf      += Wf_msg[t * 32 + j] * Wpf[j];
        }
        w1c[t] = Wnp[t] + vroot_b + vroot_f;
        wbm[t] = vb;
        wfm[t] = vf;
    }
    __syncthreads();

    {
        float s0 = 0.f, sb = 0.f, sf = 0.f;
        for (int k = 0; k < 32; k++) {
            float wm = Wm[t * 32 + k];
            s0 = fmaf(wm, w1c[k], s0);
            sb = fmaf(wm, wbm[k], sb);
            sf = fmaf(wm, wfm[k], sf);
        }
        g_u0[t] = s0; g_ub[t] = sb; g_uf[t] = sf;
    }

    if (t == 0) {
        float c0 = bnp[0] + bpb[0] + bpf[0];
        float cb = 0.f, cf = 0.f;
        for (int k = 0; k < 32; k++) {
            c0 += bm[k] * w1c[k] + bb[k] * Wpb[k] + bf[k] * Wpf[k];
            cb += bm[k] * wbm[k];
            cf += bm[k] * wfm[k];
        }
        g_c[0] = c0; g_c[1] = cb; g_c[2] = cf;
    }
    if (t < 5) g_stats[t] = 0.0;
}

// ---------------- K2: rank-2 attention, 4 blocks per graph -----------------
__global__ void k2_attn(const float* __restrict__ x)
{
    __shared__ float2 xs[NPG];
    __shared__ double wsum[8][5];
    const int g = blockIdx.x >> 2;
    const int q = blockIdx.x & 3;
    const int t = threadIdx.x;
    const float* xg = x + (size_t)g * NPG * 2;

    for (int j = t; j < NPG; j += 256)
        xs[j] = make_float2(xg[2 * j], xg[2 * j + 1]);
    __syncthreads();

    const int i = q * 256 + t;
    const float2 xi = xs[i];
    const float inv = rsqrtf((float)HIDDEN);
    const float M00 = g_M[0], M01 = g_M[1], M10 = g_M[2], M11 = g_M[3];
    const float u0 = (xi.x * M00 + xi.y * M10) * inv;
    const float u1 = (xi.x * M01 + xi.y * M11) * inv;

    float m = -1e30f;
    for (int j = 0; j < NPG; j++) {
        float2 xj = xs[j];
        m = fmaxf(m, fmaf(u0, xj.x, u1 * xj.y));
    }
    float l = 0.f, a0 = 0.f, a1 = 0.f;
    for (int j = 0; j < NPG; j++) {
        float2 xj = xs[j];
        float s = fmaf(u0, xj.x, u1 * xj.y);
        float p = __expf(s - m);
        l += p; a0 = fmaf(p, xj.x, a0); a1 = fmaf(p, xj.y, a1);
    }
    const float y0 = a0 / l, y1 = a1 / l;
    g_y[g * NPG + i] = make_float2(y0, y1);

    float v[5] = {y0, y1, y0 * y0, y0 * y1, y1 * y1};
    const int lane = t & 31, wrp = t >> 5;
    #pragma unroll
    for (int k = 0; k < 5; k++) {
        float s = v[k];
        for (int off = 16; off; off >>= 1) s += __shfl_down_sync(0xffffffffu, s, off);
        if (lane == 0) wsum[wrp][k] = (double)s;
    }
    __syncthreads();
    if (t == 0) {
        #pragma unroll
        for (int k = 0; k < 5; k++) {
            double s = 0.0;
            for (int w = 0; w < 8; w++) s += wsum[w][k];
            atomicAdd(&g_stats[k], s);
        }
    }
}

// ---------------- K3: normalize + int8 quantize, warp-per-row --------------
// NOTE: globals referenced in DEVICE code (host cannot take __device__ addresses)
__device__ __forceinline__ unsigned int pack4(float4 a, float qs)
{
    int x = __float2int_rn(a.x * qs);
    int y = __float2int_rn(a.y * qs);
    int z = __float2int_rn(a.z * qs);
    int w = __float2int_rn(a.w * qs);
    return (unsigned int)((x & 0xFF) | ((y & 0xFF) << 8) | ((z & 0xFF) << 16) | ((w & 0xFF) << 24));
}

template<int F4, bool BODY>   // float4 per lane: body 16, face 4
__global__ void k3_norm(const float* __restrict__ vis)
{
    int4*  __restrict__ qout  = BODY ? g_qb  : g_qf;
    float* __restrict__ scout = BODY ? g_scb : g_scf;

    const int w = (blockIdx.x * blockDim.x + threadIdx.x) >> 5;   // row id
    const int lane = threadIdx.x & 31;
    const float4* row = (const float4*)(vis + (size_t)w * (F4 * 128));

    float4 v[F4];
    #pragma unroll
    for (int i = 0; i < F4; i++) v[i] = __ldcs(&row[i * 32 + lane]);

    float ss = 0.f, mx = 0.f;
    #pragma unroll
    for (int i = 0; i < F4; i++) {
        float4 a = v[i];
        ss += a.x*a.x + a.y*a.y + a.z*a.z + a.w*a.w;
        mx = fmaxf(mx, fmaxf(fmaxf(fabsf(a.x), fabsf(a.y)), fmaxf(fabsf(a.z), fabsf(a.w))));
    }
    #pragma unroll
    for (int o = 16; o; o >>= 1) {
        ss += __shfl_xor_sync(0xffffffffu, ss, o);
        mx = fmaxf(mx, __shfl_xor_sync(0xffffffffu, mx, o));
    }
    mx = fmaxf(mx, 1e-20f);
    const float qs = 127.f / mx;

    unsigned int* o = (unsigned int*)(qout + (size_t)w * (F4 * 8));
    #pragma unroll
    for (int i = 0; i < F4; i++) o[i * 32 + lane] = pack4(v[i], qs);
    if (lane == 0) scout[w] = mx * rsqrtf(ss + 1e-8f) * (1.f / 127.f);
}

// ---------------- edge counting sort ----------------------------------------
__global__ void k_zero()
{
    const int n = blockIdx.x * 512 + threadIdx.x;
    if (n < N_NODES) { g_cntb[n] = 0; g_cntf[n] = 0; }
}

__global__ void k_hist(const int* __restrict__ eb, const int* __restrict__ ef, int E)
{
    const int e = blockIdx.x * 512 + threadIdx.x;
    if (e < E) {
        atomicAdd(&g_cntb[eb[E + e]], 1);
        atomicAdd(&g_cntf[ef[E + e]], 1);
    }
}

__global__ void k_scan()   // <<<2, 1024>>> : block 0 = body, block 1 = face
{
    __shared__ int part[1024];
    const int t = threadIdx.x;
    int* cnt = blockIdx.x ? g_cntf : g_cntb;
    int* off = blockIdx.x ? g_offf : g_offb;
    int* cur = blockIdx.x ? g_curf : g_curb;
    const int base = t * 32;
    int local[32];
    int s = 0;
    #pragma unroll
    for (int i = 0; i < 32; i++) { local[i] = cnt[base + i]; s += local[i]; }
    part[t] = s;
    __syncthreads();
    for (int d = 1; d < 1024; d <<= 1) {
        int v = (t >= d) ? part[t - d] : 0;
        __syncthreads();
        part[t] += v;
        __syncthreads();
    }
    int run = (t > 0) ? part[t - 1] : 0;
    #pragma unroll
    for (int i = 0; i < 32; i++) {
        off[base + i] = run;
        cur[base + i] = run;
        run += local[i];
    }
    if (t == 1023) off[N_NODES] = run;
}

__global__ void k_scatter(const int* __restrict__ eb, const int* __restrict__ ef, int E)
{
    const int e = blockIdx.x * 512 + threadIdx.x;
    if (e < E) {
        int sb = eb[e], db = eb[E + e];
        g_esb[atomicAdd(&g_curb[db], 1)] = sb;
        int sf = ef[e], df = ef[E + e];
        g_esf[atomicAdd(&g_curf[df], 1)] = sf;
    }
}

// ---------------- K4: per-node BN + PReLU + 3 scalar projections -----------
__global__ void k4_node(const float* __restrict__ Wv,
                        const float* __restrict__ gamma,
                        const float* __restrict__ beta,
                        const float* __restrict__ prelu_a)
{
    __shared__ float A0[HIDDEN], A1[HIDDEN], D[HIDDEN];
    __shared__ float U0[HIDDEN], UB[HIDDEN], UF[HIDDEN];
    const int t = threadIdx.x; // 256

    const double invN = 1.0 / (double)N_NODES;
    const double m0 = g_stats[0] * invN, m1 = g_stats[1] * invN;
    const double C00 = g_stats[2] * invN - m0 * m0;
    const double C01 = g_stats[3] * invN - m0 * m1;
    const double C11 = g_stats[4] * invN - m1 * m1;

    for (int h = t; h < HIDDEN; h += 256) {
        const float w0 = Wv[h], w1 = Wv[HIDDEN + h];
        const float var = (float)((double)w0 * w0 * C00 + 2.0 * w0 * w1 * C01 + (double)w1 * w1 * C11);
        const float mu  = (float)((double)w0 * m0 + (double)w1 * m1);
        const float gg  = gamma[h] * rsqrtf(var + 1e-5f);
        A0[h] = w0 * gg;
        A1[h] = w1 * gg;
        D[h]  = beta[h] - mu * gg;
        U0[h] = g_u0[h]; UB[h] = g_ub[h]; UF[h] = g_uf[h];
    }
    __syncthreads();

    const int n = blockIdx.x * 256 + t;
    const float2 y = g_y[n];
    const float aa = prelu_a[0];
    float acc0 = 0.f, accb = 0.f, accf = 0.f;
    #pragma unroll 8
    for (int h = 0; h < HIDDEN; h++) {
        float v = fmaf(A0[h], y.x, fmaf(A1[h], y.y, D[h]));
        v = (v >= 0.f) ? v : aa * v;
        acc0 = fmaf(v, U0[h], acc0);
        accb = fmaf(v, UB[h], accb);
        accf = fmaf(v, UF[h], accf);
    }
    g_score0[n] = acc0 + g_c[0];
    g_ssb[n]    = (accb + g_c[1]) * g_scb[n];   // fold src dequant scale into s
    g_ssf[n]    = (accf + g_c[2]) * g_scf[n];
}

// ---------------- K5: dst-grouped int8 cosine message passing --------------
// One warp per dst node; dst row in registers; src rows gathered via L2 (.cg).
// 2-edge unroll to double outstanding loads per lane.
template<int ROWI4, bool BODY>   // ROWI4 = int4 per row (128 body / 32 face)
__global__ void k5_sorted()
{
    const int wid = (blockIdx.x * blockDim.x + threadIdx.x) >> 5;
    const int lane = threadIdx.x & 31;
    if (wid >= N_NODES) return;

    const int4*  __restrict__ q      = BODY ? g_qb  : g_qf;
    const int*   __restrict__ off    = BODY ? g_offb : g_offf;
    const int*   __restrict__ sorted = BODY ? g_esb : g_esf;
    const float* __restrict__ ss     = BODY ? g_ssb : g_ssf;
    const float* __restrict__ sc     = BODY ? g_scb : g_scf;
    float*       __restrict__ msg    = BODY ? g_msgb : g_msgf;

    constexpr int C = ROWI4 / 32;   // int4 chunks per lane
    int4 dreg[C];
    #pragma unroll
    for (int c = 0; c < C; c++)
        dreg[c] = q[(size_t)wid * ROWI4 + c * 32 + lane];

    const int start = off[wid], end = off[wid + 1];
    float fl = 0.f;
    int e = start;
    for (; e + 1 < end; e += 2) {
        const int s0 = sorted[e];
        const int s1 = sorted[e + 1];
        const int4* p0 = q + (size_t)s0 * ROWI4 + lane;
        const int4* p1 = q + (size_t)s1 * ROWI4 + lane;
        int id0 = 0, id1 = 0;
        #pragma unroll
        for (int c = 0; c < C; c++) {
            int4 a = __ldcg(&p0[c * 32]);
            int4 b = __ldcg(&p1[c * 32]);
            id0 = __dp4a(a.x, dreg[c].x, id0);
            id0 = __dp4a(a.y, dreg[c].y, id0);
            id0 = __dp4a(a.z, dreg[c].z, id0);
            id0 = __dp4a(a.w, dreg[c].w, id0);
            id1 = __dp4a(b.x, dreg[c].x, id1);
            id1 = __dp4a(b.y, dreg[c].y, id1);
            id1 = __dp4a(b.z, dreg[c].z, id1);
            id1 = __dp4a(b.w, dreg[c].w, id1);
        }
        fl = fmaf((float)id0, __ldg(&ss[s0]), fl);
        fl = fmaf((float)id1, __ldg(&ss[s1]), fl);
    }
    if (e < end) {
        const int s0 = sorted[e];
        const int4* p0 = q + (size_t)s0 * ROWI4 + lane;
        int id0 = 0;
        #pragma unroll
        for (int c = 0; c < C; c++) {
            int4 a = __ldcg(&p0[c * 32]);
            id0 = __dp4a(a.x, dreg[c].x, id0);
            id0 = __dp4a(a.y, dreg[c].y, id0);
            id0 = __dp4a(a.z, dreg[c].z, id0);
            id0 = __dp4a(a.w, dreg[c].w, id0);
        }
        fl = fmaf((float)id0, __ldg(&ss[s0]), fl);
    }
    for (int o = 16; o; o >>= 1) fl += __shfl_down_sync(0xffffffffu, fl, o);
    if (lane == 0) msg[wid] = fl * sc[wid];
}

// ---------------- K6: final combine ----------------------------------------
__global__ void k6_final(float* __restrict__ out)
{
    const int n = blockIdx.x * 256 + threadIdx.x;
    const float db = (float)(g_offb[n + 1] - g_offb[n]);
    const float df = (float)(g_offf[n + 1] - g_offf[n]);
    out[n] = g_score0[n]
           + g_msgb[n] / fmaxf(db, 1.0f)
           + g_msgf[n] / fmaxf(df, 1.0f);
}

// ---------------- launch ----------------------------------------------------
extern "C" void kernel_launch(void* const* d_in, const int* in_sizes, int n_in,
                              void* d_out, int out_size)
{
    const float* x        = (const float*)d_in[0];
    const float* vis_body = (const float*)d_in[1];
    const float* vis_face = (const float*)d_in[2];
    const int*   edge_b   = (const int*)d_in[3];
    const int*   edge_f   = (const int*)d_in[4];
    const int E = in_sizes[3] / 2;

    int base = 5;
    if (n_in > 5 && in_sizes[5] == 1) base = 6;
    const float* Wq      = (const float*)d_in[base + 0];
    const float* Wk      = (const float*)d_in[base + 1];
    const float* Wv      = (const float*)d_in[base + 2];
    const float* gamma   = (const float*)d_in[base + 3];
    const float* beta    = (const float*)d_in[base + 4];
    const float* prelu_a = (const float*)d_in[base + 5];
    const float* Wm      = (const float*)d_in[base + 6];
    const float* bm      = (const float*)d_in[base + 7];
    const float* Wnp     = (const float*)d_in[base + 8];
    const float* bnp     = (const float*)d_in[base + 9];
    const float* Wb_root = (const float*)d_in[base + 10];
    const float* Wb_msg  = (const float*)d_in[base + 11];
    const float* bb      = (const float*)d_in[base + 12];
    const float* Wf_root = (const float*)d_in[base + 13];
    const float* Wf_msg  = (const float*)d_in[base + 14];
    const float* bf      = (const float*)d_in[base + 15];
    const float* Wpb     = (const float*)d_in[base + 16];
    const float* bpb     = (const float*)d_in[base + 17];
    const float* Wpf     = (const float*)d_in[base + 18];
    const float* bpf     = (const float*)d_in[base + 19];

    k1_precompute<<<1, 512>>>(Wq, Wk, Wm, bm, Wnp, bnp,
                              Wb_root, Wb_msg, bb, Wf_root, Wf_msg, bf,
                              Wpb, bpb, Wpf, bpf);
    k2_attn<<<128, 256>>>(x);
    k3_norm<16, true ><<<N_NODES / 8, 256>>>(vis_body);
    k3_norm<4,  false><<<N_NODES / 8, 256>>>(vis_face);

    k_zero<<<(N_NODES + 511) / 512, 512>>>();
    k_hist<<<(E + 511) / 512, 512>>>(edge_b, edge_f, E);
    k_scan<<<2, 1024>>>();
    k_scatter<<<(E + 511) / 512, 512>>>(edge_b, edge_f, E);

    k4_node<<<N_NODES / 256, 256>>>(Wv, gamma, beta, prelu_a);

    k5_sorted<VBDIM / 16, true ><<<N_NODES / 8, 256>>>();
    k5_sorted<VFDIM / 16, false><<<N_NODES / 8, 256>>>();

    k6_final<<<N_NODES / 256, 256>>>((float*)d_out);
}

// round 6
// speedup vs baseline: 2.1983x; 1.0066x over previous
#include <cuda_runtime.h>
#include <cuda_fp16.h>
#include <cstdint>
#include <cstddef>

#define N_NODES 32768
#define NPG     1024
#define HIDDEN  512
#define VBDIM   2048
#define VFDIM   512
#define EDGES   (N_NODES * 32)

// ---------------- scratch (device globals; no allocation allowed) ----------
__device__ int4   g_qb[(size_t)N_NODES * VBDIM / 16];  // int8 quantized body rows
__device__ int4   g_qf[(size_t)N_NODES * VFDIM / 16];  // int8 quantized face rows
__device__ float  g_scb[N_NODES], g_scf[N_NODES];      // per-row dequant scale (incl. L2 norm)
__device__ float2 g_y[N_NODES];                        // attention output (rank-2)
__device__ float  g_score0[N_NODES];
__device__ float  g_ssb[N_NODES], g_ssf[N_NODES];      // scale_src * s_src, premultiplied
__device__ float  g_msgb[N_NODES];
__device__ double g_stats[5];
__device__ float  g_M[4];
__device__ float  g_u0[HIDDEN], g_ub[HIDDEN], g_uf[HIDDEN];
__device__ float  g_c[3];
// edge sorting
__device__ int g_cntb[N_NODES], g_cntf[N_NODES];
__device__ int g_offb[N_NODES + 1], g_offf[N_NODES + 1];
__device__ int g_curb[N_NODES], g_curf[N_NODES];
__device__ int g_esb[EDGES], g_esf[EDGES];

// ---------------- K1: tiny weight precompute (1 block, 512 threads) --------
__global__ void k1_precompute(
    const float* __restrict__ Wq,  const float* __restrict__ Wk,
    const float* __restrict__ Wm,  const float* __restrict__ bm,
    const float* __restrict__ Wnp, const float* __restrict__ bnp,
    const float* __restrict__ Wb_root, const float* __restrict__ Wb_msg, const float* __restrict__ bb,
    const float* __restrict__ Wf_root, const float* __restrict__ Wf_msg, const float* __restrict__ bf,
    const float* __restrict__ Wpb, const float* __restrict__ bpb,
    const float* __restrict__ Wpf, const float* __restrict__ bpf)
{
    __shared__ float red[512];
    __shared__ float w1c[32], wbm[32], wfm[32];
    const int t = threadIdx.x;

    for (int a = 0; a < 2; a++) {
        for (int b = 0; b < 2; b++) {
            red[t] = Wq[a * HIDDEN + t] * Wk[b * HIDDEN + t];
            __syncthreads();
            for (int s = 256; s > 0; s >>= 1) {
                if (t < s) red[t] += red[t + s];
                __syncthreads();
            }
            if (t == 0) g_M[a * 2 + b] = red[0];
            __syncthreads();
        }
    }

    if (t < 32) {
        float vroot_b = 0.f, vroot_f = 0.f, vb = 0.f, vf = 0.f;
        for (int j = 0; j < 32; j++) {
            vroot_b += Wb_root[t * 32 + j] * Wpb[j];
            vroot_f += Wf_root[t * 32 + j] * Wpf[j];
            vb      += Wb_msg[t * 32 + j] * Wpb[j];
            vf      += Wf_msg[t * 32 + j] * Wpf[j];
        }
        w1c[t] = Wnp[t] + vroot_b + vroot_f;
        wbm[t] = vb;
        wfm[t] = vf;
    }
    __syncthreads();

    {
        float s0 = 0.f, sb = 0.f, sf = 0.f;
        for (int k = 0; k < 32; k++) {
            float wm = Wm[t * 32 + k];
            s0 = fmaf(wm, w1c[k], s0);
            sb = fmaf(wm, wbm[k], sb);
            sf = fmaf(wm, wfm[k], sf);
        }
        g_u0[t] = s0; g_ub[t] = sb; g_uf[t] = sf;
    }

    if (t == 0) {
        float c0 = bnp[0] + bpb[0] + bpf[0];
        float cb = 0.f, cf = 0.f;
        for (int k = 0; k < 32; k++) {
            c0 += bm[k] * w1c[k] + bb[k] * Wpb[k] + bf[k] * Wpf[k];
            cb += bm[k] * wbm[k];
            cf += bm[k] * wfm[k];
        }
        g_c[0] = c0; g_c[1] = cb; g_c[2] = cf;
    }
    if (t < 5) g_stats[t] = 0.0;
}

// ---------------- K2: rank-2 attention, 4 blocks per graph -----------------
// Exactly 32768 threads: also zeroes the sort counters.
__global__ void k2_attn(const float* __restrict__ x)
{
    __shared__ float2 xs[NPG];
    __shared__ double wsum[8][5];
    const int g = blockIdx.x >> 2;
    const int q = blockIdx.x & 3;
    const int t = threadIdx.x;
    const float* xg = x + (size_t)g * NPG * 2;

    const int nidx = blockIdx.x * 256 + t;   // 0..32767
    g_cntb[nidx] = 0;
    g_cntf[nidx] = 0;

    for (int j = t; j < NPG; j += 256)
        xs[j] = make_float2(xg[2 * j], xg[2 * j + 1]);
    __syncthreads();

    const int i = q * 256 + t;
    const float2 xi = xs[i];
    const float inv = rsqrtf((float)HIDDEN);
    const float M00 = g_M[0], M01 = g_M[1], M10 = g_M[2], M11 = g_M[3];
    const float u0 = (xi.x * M00 + xi.y * M10) * inv;
    const float u1 = (xi.x * M01 + xi.y * M11) * inv;

    float m = -1e30f;
    for (int j = 0; j < NPG; j++) {
        float2 xj = xs[j];
        m = fmaxf(m, fmaf(u0, xj.x, u1 * xj.y));
    }
    float l = 0.f, a0 = 0.f, a1 = 0.f;
    for (int j = 0; j < NPG; j++) {
        float2 xj = xs[j];
        float s = fmaf(u0, xj.x, u1 * xj.y);
        float p = __expf(s - m);
        l += p; a0 = fmaf(p, xj.x, a0); a1 = fmaf(p, xj.y, a1);
    }
    const float y0 = a0 / l, y1 = a1 / l;
    g_y[g * NPG + i] = make_float2(y0, y1);

    float v[5] = {y0, y1, y0 * y0, y0 * y1, y1 * y1};
    const int lane = t & 31, wrp = t >> 5;
    #pragma unroll
    for (int k = 0; k < 5; k++) {
        float s = v[k];
        for (int off = 16; off; off >>= 1) s += __shfl_down_sync(0xffffffffu, s, off);
        if (lane == 0) wsum[wrp][k] = (double)s;
    }
    __syncthreads();
    if (t == 0) {
        #pragma unroll
        for (int k = 0; k < 5; k++) {
            double s = 0.0;
            for (int w = 0; w < 8; w++) s += wsum[w][k];
            atomicAdd(&g_stats[k], s);
        }
    }
}

// ---------------- K3: normalize + int8 quantize, warp-per-row --------------
// SORTMODE 1: piggyback dst histogram (both edge lists) — thread count == E
// SORTMODE 2: piggyback edge scatter (both edge lists)  — thread count == E
__device__ __forceinline__ unsigned int pack4(float4 a, float qs)
{
    int x = __float2int_rn(a.x * qs);
    int y = __float2int_rn(a.y * qs);
    int z = __float2int_rn(a.z * qs);
    int w = __float2int_rn(a.w * qs);
    return (unsigned int)((x & 0xFF) | ((y & 0xFF) << 8) | ((z & 0xFF) << 16) | ((w & 0xFF) << 24));
}

template<int F4, bool BODY, int SORTMODE>   // float4 per lane: body 16, face 4
__global__ void __launch_bounds__(256) k3_norm(const float* __restrict__ vis,
                                               const int* __restrict__ eb,
                                               const int* __restrict__ ef, int E)
{
    int4*  __restrict__ qout  = BODY ? g_qb  : g_qf;
    float* __restrict__ scout = BODY ? g_scb : g_scf;

    const int tid = blockIdx.x * blockDim.x + threadIdx.x;
    const int w = tid >> 5;   // row id
    const int lane = threadIdx.x & 31;
    const float4* row = (const float4*)(vis + (size_t)w * (F4 * 128));

    // issue row loads first so they are in flight during the sort ops
    float4 v[F4];
    #pragma unroll
    for (int i = 0; i < F4; i++) v[i] = __ldcs(&row[i * 32 + lane]);

    if (SORTMODE == 1 && tid < E) {
        atomicAdd(&g_cntb[eb[E + tid]], 1);
        atomicAdd(&g_cntf[ef[E + tid]], 1);
    }
    if (SORTMODE == 2 && tid < E) {
        const int sb = eb[tid], db = eb[E + tid];
        g_esb[atomicAdd(&g_curb[db], 1)] = sb;
        const int sf = ef[tid], df = ef[E + tid];
        g_esf[atomicAdd(&g_curf[df], 1)] = sf;
    }

    float ss = 0.f, mx = 0.f;
    #pragma unroll
    for (int i = 0; i < F4; i++) {
        float4 a = v[i];
        ss += a.x*a.x + a.y*a.y + a.z*a.z + a.w*a.w;
        mx = fmaxf(mx, fmaxf(fmaxf(fabsf(a.x), fabsf(a.y)), fmaxf(fabsf(a.z), fabsf(a.w))));
    }
    #pragma unroll
    for (int o = 16; o; o >>= 1) {
        ss += __shfl_xor_sync(0xffffffffu, ss, o);
        mx = fmaxf(mx, __shfl_xor_sync(0xffffffffu, mx, o));
    }
    mx = fmaxf(mx, 1e-20f);
    const float qs = 127.f / mx;

    unsigned int* o = (unsigned int*)(qout + (size_t)w * (F4 * 8));
    #pragma unroll
    for (int i = 0; i < F4; i++) o[i * 32 + lane] = pack4(v[i], qs);
    if (lane == 0) scout[w] = mx * rsqrtf(ss + 1e-8f) * (1.f / 127.f);
}

// ---------------- scan: offsets from counts (2 blocks) ----------------------
__global__ void k_scan()   // <<<2, 1024>>> : block 0 = body, block 1 = face
{
    __shared__ int part[1024];
    const int t = threadIdx.x;
    int* cnt = blockIdx.x ? g_cntf : g_cntb;
    int* off = blockIdx.x ? g_offf : g_offb;
    int* cur = blockIdx.x ? g_curf : g_curb;
    const int base = t * 32;
    int local[32];
    int s = 0;
    #pragma unroll
    for (int i = 0; i < 32; i++) { local[i] = cnt[base + i]; s += local[i]; }
    part[t] = s;
    __syncthreads();
    for (int d = 1; d < 1024; d <<= 1) {
        int v = (t >= d) ? part[t - d] : 0;
        __syncthreads();
        part[t] += v;
        __syncthreads();
    }
    int run = (t > 0) ? part[t - 1] : 0;
    #pragma unroll
    for (int i = 0; i < 32; i++) {
        off[base + i] = run;
        cur[base + i] = run;
        run += local[i];
    }
    if (t == 1023) off[N_NODES] = run;
}

// ---------------- K4: per-node BN + PReLU + 3 scalar projections -----------
__global__ void k4_node(const float* __restrict__ Wv,
                        const float* __restrict__ gamma,
                        const float* __restrict__ beta,
                        const float* __restrict__ prelu_a)
{
    __shared__ float A0[HIDDEN], A1[HIDDEN], D[HIDDEN];
    __shared__ float U0[HIDDEN], UB[HIDDEN], UF[HIDDEN];
    const int t = threadIdx.x; // 256

    const double invN = 1.0 / (double)N_NODES;
    const double m0 = g_stats[0] * invN, m1 = g_stats[1] * invN;
    const double C00 = g_stats[2] * invN - m0 * m0;
    const double C01 = g_stats[3] * invN - m0 * m1;
    const double C11 = g_stats[4] * invN - m1 * m1;

    for (int h = t; h < HIDDEN; h += 256) {
        const float w0 = Wv[h], w1 = Wv[HIDDEN + h];
        const float var = (float)((double)w0 * w0 * C00 + 2.0 * w0 * w1 * C01 + (double)w1 * w1 * C11);
        const float mu  = (float)((double)w0 * m0 + (double)w1 * m1);
        const float gg  = gamma[h] * rsqrtf(var + 1e-5f);
        A0[h] = w0 * gg;
        A1[h] = w1 * gg;
        D[h]  = beta[h] - mu * gg;
        U0[h] = g_u0[h]; UB[h] = g_ub[h]; UF[h] = g_uf[h];
    }
    __syncthreads();

    const int n = blockIdx.x * 256 + t;
    const float2 y = g_y[n];
    const float aa = prelu_a[0];
    float acc0 = 0.f, accb = 0.f, accf = 0.f;
    #pragma unroll 8
    for (int h = 0; h < HIDDEN; h++) {
        float v = fmaf(A0[h], y.x, fmaf(A1[h], y.y, D[h]));
        v = (v >= 0.f) ? v : aa * v;
        acc0 = fmaf(v, U0[h], acc0);
        accb = fmaf(v, UB[h], accb);
        accf = fmaf(v, UF[h], accf);
    }
    g_score0[n] = acc0 + g_c[0];
    g_ssb[n]    = (accb + g_c[1]) * g_scb[n];   // fold src dequant scale into s
    g_ssf[n]    = (accf + g_c[2]) * g_scf[n];
}

// ---------------- K5: dst-grouped int8 cosine message passing --------------
// One warp per dst node; dst row in registers; src rows gathered via L2 (.cg).
// FINAL=true (face pass): lane 0 emits the fused final output.
template<int ROWI4, bool BODY, bool FINAL>
__global__ void k5_sorted(float* __restrict__ out)
{
    const int wid = (blockIdx.x * blockDim.x + threadIdx.x) >> 5;
    const int lane = threadIdx.x & 31;
    if (wid >= N_NODES) return;

    const int4*  __restrict__ q      = BODY ? g_qb  : g_qf;
    const int*   __restrict__ off    = BODY ? g_offb : g_offf;
    const int*   __restrict__ sorted = BODY ? g_esb : g_esf;
    const float* __restrict__ ss     = BODY ? g_ssb : g_ssf;
    const float* __restrict__ sc     = BODY ? g_scb : g_scf;

    constexpr int C = ROWI4 / 32;   // int4 chunks per lane
    int4 dreg[C];
    #pragma unroll
    for (int c = 0; c < C; c++)
        dreg[c] = q[(size_t)wid * ROWI4 + c * 32 + lane];

    const int start = off[wid], end = off[wid + 1];
    float fl = 0.f;
    int e = start;
    for (; e + 1 < end; e += 2) {
        const int s0 = sorted[e];
        const int s1 = sorted[e + 1];
        const int4* p0 = q + (size_t)s0 * ROWI4 + lane;
        const int4* p1 = q + (size_t)s1 * ROWI4 + lane;
        int id0 = 0, id1 = 0;
        #pragma unroll
        for (int c = 0; c < C; c++) {
            int4 a = __ldcg(&p0[c * 32]);
            int4 b = __ldcg(&p1[c * 32]);
            id0 = __dp4a(a.x, dreg[c].x, id0);
            id0 = __dp4a(a.y, dreg[c].y, id0);
            id0 = __dp4a(a.z, dreg[c].z, id0);
            id0 = __dp4a(a.w, dreg[c].w, id0);
            id1 = __dp4a(b.x, dreg[c].x, id1);
            id1 = __dp4a(b.y, dreg[c].y, id1);
            id1 = __dp4a(b.z, dreg[c].z, id1);
            id1 = __dp4a(b.w, dreg[c].w, id1);
        }
        fl = fmaf((float)id0, __ldg(&ss[s0]), fl);
        fl = fmaf((float)id1, __ldg(&ss[s1]), fl);
    }
    if (e < end) {
        const int s0 = sorted[e];
        const int4* p0 = q + (size_t)s0 * ROWI4 + lane;
        int id0 = 0;
        #pragma unroll
        for (int c = 0; c < C; c++) {
            int4 a = __ldcg(&p0[c * 32]);
            id0 = __dp4a(a.x, dreg[c].x, id0);
            id0 = __dp4a(a.y, dreg[c].y, id0);
            id0 = __dp4a(a.z, dreg[c].z, id0);
            id0 = __dp4a(a.w, dreg[c].w, id0);
        }
        fl = fmaf((float)id0, __ldg(&ss[s0]), fl);
    }
    for (int o = 16; o; o >>= 1) fl += __shfl_down_sync(0xffffffffu, fl, o);
    if (lane == 0) {
        if (FINAL) {
            const float msgf = fl * sc[wid];
            const float db = (float)(g_offb[wid + 1] - g_offb[wid]);
            const float df = (float)(end - start);
            out[wid] = g_score0[wid]
                     + g_msgb[wid] / fmaxf(db, 1.0f)
                     + msgf / fmaxf(df, 1.0f);
        } else {
            g_msgb[wid] = fl * sc[wid];
        }
    }
}

// ---------------- launch ----------------------------------------------------
extern "C" void kernel_launch(void* const* d_in, const int* in_sizes, int n_in,
                              void* d_out, int out_size)
{
    const float* x        = (const float*)d_in[0];
    const float* vis_body = (const float*)d_in[1];
    const float* vis_face = (const float*)d_in[2];
    const int*   edge_b   = (const int*)d_in[3];
    const int*   edge_f   = (const int*)d_in[4];
    const int E = in_sizes[3] / 2;

    int base = 5;
    if (n_in > 5 && in_sizes[5] == 1) base = 6;
    const float* Wq      = (const float*)d_in[base + 0];
    const float* Wk      = (const float*)d_in[base + 1];
    const float* Wv      = (const float*)d_in[base + 2];
    const float* gamma   = (const float*)d_in[base + 3];
    const float* beta    = (const float*)d_in[base + 4];
    const float* prelu_a = (const float*)d_in[base + 5];
    const float* Wm      = (const float*)d_in[base + 6];
    const float* bm      = (const float*)d_in[base + 7];
    const float* Wnp     = (const float*)d_in[base + 8];
    const float* bnp     = (const float*)d_in[base + 9];
    const float* Wb_root = (const float*)d_in[base + 10];
    const float* Wb_msg  = (const float*)d_in[base + 11];
    const float* bb      = (const float*)d_in[base + 12];
    const float* Wf_root = (const float*)d_in[base + 13];
    const float* Wf_msg  = (const float*)d_in[base + 14];
    const float* bf      = (const float*)d_in[base + 15];
    const float* Wpb     = (const float*)d_in[base + 16];
    const float* bpb     = (const float*)d_in[base + 17];
    const float* Wpf     = (const float*)d_in[base + 18];
    const float* bpf     = (const float*)d_in[base + 19];

    k1_precompute<<<1, 512>>>(Wq, Wk, Wm, bm, Wnp, bnp,
                              Wb_root, Wb_msg, bb, Wf_root, Wf_msg, bf,
                              Wpb, bpb, Wpf, bpf);
    k2_attn<<<128, 256>>>(x);                                      // + zero counters
    k3_norm<16, true,  1><<<N_NODES / 8, 256>>>(vis_body, edge_b, edge_f, E); // + hist
    k_scan<<<2, 1024>>>();
    k3_norm<4,  false, 2><<<N_NODES / 8, 256>>>(vis_face, edge_b, edge_f, E); // + scatter
    k4_node<<<N_NODES / 256, 256>>>(Wv, gamma, beta, prelu_a);
    k5_sorted<VBDIM / 16, true,  false><<<N_NODES / 8, 256>>>(nullptr);
    k5_sorted<VFDIM / 16, false, true ><<<N_NODES / 8, 256>>>((float*)d_out); // + final combine
}

// round 7
// speedup vs baseline: 2.5744x; 1.1711x over previous
#include <cuda_runtime.h>
#include <cuda_fp16.h>
#include <cstdint>
#include <cstddef>

#define N_NODES 32768
#define NPG     1024
#define HIDDEN  512
#define VBDIM   2048
#define VFDIM   512
#define EDGES   (N_NODES * 32)

// ---------------- scratch (device globals; no allocation allowed) ----------
__device__ int4   g_qb[(size_t)N_NODES * VBDIM / 16];  // int8 quantized body rows
__device__ int4   g_qf[(size_t)N_NODES * VFDIM / 16];  // int8 quantized face rows
__device__ float  g_scb[N_NODES], g_scf[N_NODES];      // per-row dequant scale (incl. L2 norm)
__device__ float2 g_y[N_NODES];                        // attention output (rank-2)
__device__ float  g_score0[N_NODES];
__device__ float  g_ssb[N_NODES], g_ssf[N_NODES];      // scale_src * s_src, premultiplied
__device__ float  g_msgb[N_NODES];
__device__ double g_stats[5];
__device__ float  g_M[4];
__device__ float  g_u0[HIDDEN], g_ub[HIDDEN], g_uf[HIDDEN];
__device__ float  g_c[3];
// edge sorting
__device__ int g_cntb[N_NODES], g_cntf[N_NODES];
__device__ int g_offb[N_NODES + 1], g_offf[N_NODES + 1];
__device__ int g_curb[N_NODES], g_curf[N_NODES];
__device__ int g_esb[EDGES], g_esf[EDGES];
__device__ int g_bsum[2][128], g_bpre[2][128];         // hierarchical scan temps

// ---------------- K1: tiny weight precompute (1 block, 512 threads) --------
__global__ void k1_precompute(
    const float* __restrict__ Wq,  const float* __restrict__ Wk,
    const float* __restrict__ Wm,  const float* __restrict__ bm,
    const float* __restrict__ Wnp, const float* __restrict__ bnp,
    const float* __restrict__ Wb_root, const float* __restrict__ Wb_msg, const float* __restrict__ bb,
    const float* __restrict__ Wf_root, const float* __restrict__ Wf_msg, const float* __restrict__ bf,
    const float* __restrict__ Wpb, const float* __restrict__ bpb,
    const float* __restrict__ Wpf, const float* __restrict__ bpf)
{
    __shared__ float red[512];
    __shared__ float w1c[32], wbm[32], wfm[32];
    const int t = threadIdx.x;

    for (int a = 0; a < 2; a++) {
        for (int b = 0; b < 2; b++) {
            red[t] = Wq[a * HIDDEN + t] * Wk[b * HIDDEN + t];
            __syncthreads();
            for (int s = 256; s > 0; s >>= 1) {
                if (t < s) red[t] += red[t + s];
                __syncthreads();
            }
            if (t == 0) g_M[a * 2 + b] = red[0];
            __syncthreads();
        }
    }

    if (t < 32) {
        float vroot_b = 0.f, vroot_f = 0.f, vb = 0.f, vf = 0.f;
        for (int j = 0; j < 32; j++) {
            vroot_b += Wb_root[t * 32 + j] * Wpb[j];
            vroot_f += Wf_root[t * 32 + j] * Wpf[j];
            vb      += Wb_msg[t * 32 + j] * Wpb[j];
            vf      += Wf_msg[t * 32 + j] * Wpf[j];
        }
        w1c[t] = Wnp[t] + vroot_b + vroot_f;
        wbm[t] = vb;
        wfm[t] = vf;
    }
    __syncthreads();

    {
        float s0 = 0.f, sb = 0.f, sf = 0.f;
        for (int k = 0; k < 32; k++) {
            float wm = Wm[t * 32 + k];
            s0 = fmaf(wm, w1c[k], s0);
            sb = fmaf(wm, wbm[k], sb);
            sf = fmaf(wm, wfm[k], sf);
        }
        g_u0[t] = s0; g_ub[t] = sb; g_uf[t] = sf;
    }

    if (t == 0) {
        float c0 = bnp[0] + bpb[0] + bpf[0];
        float cb = 0.f, cf = 0.f;
        for (int k = 0; k < 32; k++) {
            c0 += bm[k] * w1c[k] + bb[k] * Wpb[k] + bf[k] * Wpf[k];
            cb += bm[k] * wbm[k];
            cf += bm[k] * wfm[k];
        }
        g_c[0] = c0; g_c[1] = cb; g_c[2] = cf;
    }
    if (t < 5) g_stats[t] = 0.0;
}

// ---------------- K2: rank-2 attention, 4 blocks per graph -----------------
// Exactly 32768 threads: also zeroes the sort counters.
__global__ void k2_attn(const float* __restrict__ x)
{
    __shared__ float2 xs[NPG];
    __shared__ double wsum[8][5];
    const int g = blockIdx.x >> 2;
    const int q = blockIdx.x & 3;
    const int t = threadIdx.x;
    const float* xg = x + (size_t)g * NPG * 2;

    const int nidx = blockIdx.x * 256 + t;   // 0..32767
    g_cntb[nidx] = 0;
    g_cntf[nidx] = 0;

    for (int j = t; j < NPG; j += 256)
        xs[j] = make_float2(xg[2 * j], xg[2 * j + 1]);
    __syncthreads();

    const int i = q * 256 + t;
    const float2 xi = xs[i];
    const float inv = rsqrtf((float)HIDDEN);
    const float M00 = g_M[0], M01 = g_M[1], M10 = g_M[2], M11 = g_M[3];
    const float u0 = (xi.x * M00 + xi.y * M10) * inv;
    const float u1 = (xi.x * M01 + xi.y * M11) * inv;

    float m = -1e30f;
    for (int j = 0; j < NPG; j++) {
        float2 xj = xs[j];
        m = fmaxf(m, fmaf(u0, xj.x, u1 * xj.y));
    }
    float l = 0.f, a0 = 0.f, a1 = 0.f;
    for (int j = 0; j < NPG; j++) {
        float2 xj = xs[j];
        float s = fmaf(u0, xj.x, u1 * xj.y);
        float p = __expf(s - m);
        l += p; a0 = fmaf(p, xj.x, a0); a1 = fmaf(p, xj.y, a1);
    }
    const float y0 = a0 / l, y1 = a1 / l;
    g_y[g * NPG + i] = make_float2(y0, y1);

    float v[5] = {y0, y1, y0 * y0, y0 * y1, y1 * y1};
    const int lane = t & 31, wrp = t >> 5;
    #pragma unroll
    for (int k = 0; k < 5; k++) {
        float s = v[k];
        for (int off = 16; off; off >>= 1) s += __shfl_down_sync(0xffffffffu, s, off);
        if (lane == 0) wsum[wrp][k] = (double)s;
    }
    __syncthreads();
    if (t == 0) {
        #pragma unroll
        for (int k = 0; k < 5; k++) {
            double s = 0.0;
            for (int w = 0; w < 8; w++) s += wsum[w][k];
            atomicAdd(&g_stats[k], s);
        }
    }
}

// ---------------- K3: normalize + int8 quantize, warp-per-row --------------
// SORTMODE 1: piggyback dst histogram (both edge lists) — thread count == E
// SORTMODE 2: piggyback edge scatter (both edge lists)  — thread count == E
__device__ __forceinline__ unsigned int pack4(float4 a, float qs)
{
    int x = __float2int_rn(a.x * qs);
    int y = __float2int_rn(a.y * qs);
    int z = __float2int_rn(a.z * qs);
    int w = __float2int_rn(a.w * qs);
    return (unsigned int)((x & 0xFF) | ((y & 0xFF) << 8) | ((z & 0xFF) << 16) | ((w & 0xFF) << 24));
}

template<int F4, bool BODY, int SORTMODE>   // float4 per lane: body 16, face 4
__global__ void __launch_bounds__(256) k3_norm(const float* __restrict__ vis,
                                               const int* __restrict__ eb,
                                               const int* __restrict__ ef, int E)
{
    int4*  __restrict__ qout  = BODY ? g_qb  : g_qf;
    float* __restrict__ scout = BODY ? g_scb : g_scf;

    const int tid = blockIdx.x * blockDim.x + threadIdx.x;
    const int w = tid >> 5;   // row id
    const int lane = threadIdx.x & 31;
    const float4* row = (const float4*)(vis + (size_t)w * (F4 * 128));

    // issue row loads first so they are in flight during the sort ops
    float4 v[F4];
    #pragma unroll
    for (int i = 0; i < F4; i++) v[i] = __ldcs(&row[i * 32 + lane]);

    if (SORTMODE == 1 && tid < E) {
        atomicAdd(&g_cntb[eb[E + tid]], 1);
        atomicAdd(&g_cntf[ef[E + tid]], 1);
    }
    if (SORTMODE == 2 && tid < E) {
        const int sb = eb[tid], db = eb[E + tid];
        g_esb[atomicAdd(&g_curb[db], 1)] = sb;
        const int sf = ef[tid], df = ef[E + tid];
        g_esf[atomicAdd(&g_curf[df], 1)] = sf;
    }

    float ss = 0.f, mx = 0.f;
    #pragma unroll
    for (int i = 0; i < F4; i++) {
        float4 a = v[i];
        ss += a.x*a.x + a.y*a.y + a.z*a.z + a.w*a.w;
        mx = fmaxf(mx, fmaxf(fmaxf(fabsf(a.x), fabsf(a.y)), fmaxf(fabsf(a.z), fabsf(a.w))));
    }
    #pragma unroll
    for (int o = 16; o; o >>= 1) {
        ss += __shfl_xor_sync(0xffffffffu, ss, o);
        mx = fmaxf(mx, __shfl_xor_sync(0xffffffffu, mx, o));
    }
    mx = fmaxf(mx, 1e-20f);
    const float qs = 127.f / mx;

    unsigned int* o = (unsigned int*)(qout + (size_t)w * (F4 * 8));
    #pragma unroll
    for (int i = 0; i < F4; i++) o[i * 32 + lane] = pack4(v[i], qs);
    if (lane == 0) scout[w] = mx * rsqrtf(ss + 1e-8f) * (1.f / 127.f);
}

// ---------------- hierarchical scan (3 wide phases) --------------------------
// A: 256 blocks (128 body + 128 face) x 256 threads, local exclusive scan
__global__ void k_scanA()
{
    const int list = blockIdx.x >> 7;          // 0 body, 1 face
    const int blk  = blockIdx.x & 127;
    const int t = threadIdx.x;                 // 256
    const int idx = blk * 256 + t;
    const int* cnt = list ? g_cntf : g_cntb;
    int* off = list ? g_offf : g_offb;

    const int v = cnt[idx];
    const int lane = t & 31, wrp = t >> 5;
    int x = v;
    #pragma unroll
    for (int o = 1; o < 32; o <<= 1) {
        int y = __shfl_up_sync(0xffffffffu, x, o);
        if (lane >= o) x += y;
    }
    __shared__ int wsum[8];
    if (lane == 31) wsum[wrp] = x;
    __syncthreads();
    int wpre = 0;
    #pragma unroll
    for (int w = 0; w < 8; w++) wpre += (w < wrp) ? wsum[w] : 0;
    off[idx] = wpre + x - v;                   // local exclusive prefix
    if (t == 255) g_bsum[list][blk] = wpre + x;
}

// B: 2 blocks x 128 threads, exclusive scan of block sums
__global__ void k_scanB()
{
    const int list = blockIdx.x;
    const int t = threadIdx.x;                 // 128
    const int v = g_bsum[list][t];
    const int lane = t & 31, wrp = t >> 5;
    int x = v;
    #pragma unroll
    for (int o = 1; o < 32; o <<= 1) {
        int y = __shfl_up_sync(0xffffffffu, x, o);
        if (lane >= o) x += y;
    }
    __shared__ int wsum[4];
    if (lane == 31) wsum[wrp] = x;
    __syncthreads();
    int wpre = 0;
    #pragma unroll
    for (int w = 0; w < 4; w++) wpre += (w < wrp) ? wsum[w] : 0;
    g_bpre[list][t] = wpre + x - v;
    if (t == 127) {
        int* off = list ? g_offf : g_offb;
        off[N_NODES] = wpre + x;               // total = E
    }
}

// C: 256 blocks x 256 threads, add block prefix, write cur
__global__ void k_scanC()
{
    const int list = blockIdx.x >> 7;
    const int blk  = blockIdx.x & 127;
    const int t = threadIdx.x;
    const int idx = blk * 256 + t;
    int* off = list ? g_offf : g_offb;
    int* cur = list ? g_curf : g_curb;
    const int v = off[idx] + g_bpre[list][blk];
    off[idx] = v;
    cur[idx] = v;
}

// ---------------- K4: per-node BN + PReLU + 3 scalar projections -----------
__global__ void k4_node(const float* __restrict__ Wv,
                        const float* __restrict__ gamma,
                        const float* __restrict__ beta,
                        const float* __restrict__ prelu_a)
{
    __shared__ float A0[HIDDEN], A1[HIDDEN], D[HIDDEN];
    __shared__ float U0[HIDDEN], UB[HIDDEN], UF[HIDDEN];
    const int t = threadIdx.x; // 256

    const double invN = 1.0 / (double)N_NODES;
    const double m0 = g_stats[0] * invN, m1 = g_stats[1] * invN;
    const double C00 = g_stats[2] * invN - m0 * m0;
    const double C01 = g_stats[3] * invN - m0 * m1;
    const double C11 = g_stats[4] * invN - m1 * m1;

    for (int h = t; h < HIDDEN; h += 256) {
        const float w0 = Wv[h], w1 = Wv[HIDDEN + h];
        const float var = (float)((double)w0 * w0 * C00 + 2.0 * w0 * w1 * C01 + (double)w1 * w1 * C11);
        const float mu  = (float)((double)w0 * m0 + (double)w1 * m1);
        const float gg  = gamma[h] * rsqrtf(var + 1e-5f);
        A0[h] = w0 * gg;
        A1[h] = w1 * gg;
        D[h]  = beta[h] - mu * gg;
        U0[h] = g_u0[h]; UB[h] = g_ub[h]; UF[h] = g_uf[h];
    }
    __syncthreads();

    const int n = blockIdx.x * 256 + t;
    const float2 y = g_y[n];
    const float aa = prelu_a[0];
    float acc0 = 0.f, accb = 0.f, accf = 0.f;
    #pragma unroll 8
    for (int h = 0; h < HIDDEN; h++) {
        float v = fmaf(A0[h], y.x, fmaf(A1[h], y.y, D[h]));
        v = (v >= 0.f) ? v : aa * v;
        acc0 = fmaf(v, U0[h], acc0);
        accb = fmaf(v, UB[h], accb);
        accf = fmaf(v, UF[h], accf);
    }
    g_score0[n] = acc0 + g_c[0];
    g_ssb[n]    = (accb + g_c[1]) * g_scb[n];   // fold src dequant scale into s
    g_ssf[n]    = (accf + g_c[2]) * g_scf[n];
}

// ---------------- K5: dst-grouped int8 cosine message passing --------------
// One warp per dst node; dst row in registers; src rows gathered via L2 (.cg).
// FINAL=true (face pass): lane 0 emits the fused final output.
template<int ROWI4, bool BODY, bool FINAL>
__global__ void k5_sorted(float* __restrict__ out)
{
    const int wid = (blockIdx.x * blockDim.x + threadIdx.x) >> 5;
    const int lane = threadIdx.x & 31;
    if (wid >= N_NODES) return;

    const int4*  __restrict__ q      = BODY ? g_qb  : g_qf;
    const int*   __restrict__ off    = BODY ? g_offb : g_offf;
    const int*   __restrict__ sorted = BODY ? g_esb : g_esf;
    const float* __restrict__ ss     = BODY ? g_ssb : g_ssf;
    const float* __restrict__ sc     = BODY ? g_scb : g_scf;

    constexpr int C = ROWI4 / 32;   // int4 chunks per lane
    int4 dreg[C];
    #pragma unroll
    for (int c = 0; c < C; c++)
        dreg[c] = q[(size_t)wid * ROWI4 + c * 32 + lane];

    const int start = off[wid], end = off[wid + 1];
    float fl = 0.f;
    int e = start;
    for (; e + 1 < end; e += 2) {
        const int s0 = sorted[e];
        const int s1 = sorted[e + 1];
        const int4* p0 = q + (size_t)s0 * ROWI4 + lane;
        const int4* p1 = q + (size_t)s1 * ROWI4 + lane;
        int id0 = 0, id1 = 0;
        #pragma unroll
        for (int c = 0; c < C; c++) {
            int4 a = __ldcg(&p0[c * 32]);
            int4 b = __ldcg(&p1[c * 32]);
            id0 = __dp4a(a.x, dreg[c].x, id0);
            id0 = __dp4a(a.y, dreg[c].y, id0);
            id0 = __dp4a(a.z, dreg[c].z, id0);
            id0 = __dp4a(a.w, dreg[c].w, id0);
            id1 = __dp4a(b.x, dreg[c].x, id1);
            id1 = __dp4a(b.y, dreg[c].y, id1);
            id1 = __dp4a(b.z, dreg[c].z, id1);
            id1 = __dp4a(b.w, dreg[c].w, id1);
        }
        fl = fmaf((float)id0, __ldg(&ss[s0]), fl);
        fl = fmaf((float)id1, __ldg(&ss[s1]), fl);
    }
    if (e < end) {
        const int s0 = sorted[e];
        const int4* p0 = q + (size_t)s0 * ROWI4 + lane;
        int id0 = 0;
        #pragma unroll
        for (int c = 0; c < C; c++) {
            int4 a = __ldcg(&p0[c * 32]);
            id0 = __dp4a(a.x, dreg[c].x, id0);
            id0 = __dp4a(a.y, dreg[c].y, id0);
            id0 = __dp4a(a.z, dreg[c].z, id0);
            id0 = __dp4a(a.w, dreg[c].w, id0);
        }
        fl = fmaf((float)id0, __ldg(&ss[s0]), fl);
    }
    for (int o = 16; o; o >>= 1) fl += __shfl_down_sync(0xffffffffu, fl, o);
    if (lane == 0) {
        if (FINAL) {
            const float msgf = fl * sc[wid];
            const float db = (float)(g_offb[wid + 1] - g_offb[wid]);
            const float df = (float)(end - start);
            out[wid] = g_score0[wid]
                     + g_msgb[wid] / fmaxf(db, 1.0f)
                     + msgf / fmaxf(df, 1.0f);
        } else {
            g_msgb[wid] = fl * sc[wid];
        }
    }
}

// ---------------- launch ----------------------------------------------------
extern "C" void kernel_launch(void* const* d_in, const int* in_sizes, int n_in,
                              void* d_out, int out_size)
{
    const float* x        = (const float*)d_in[0];
    const float* vis_body = (const float*)d_in[1];
    const float* vis_face = (const float*)d_in[2];
    const int*   edge_b   = (const int*)d_in[3];
    const int*   edge_f   = (const int*)d_in[4];
    const int E = in_sizes[3] / 2;

    int base = 5;
    if (n_in > 5 && in_sizes[5] == 1) base = 6;
    const float* Wq      = (const float*)d_in[base + 0];
    const float* Wk      = (const float*)d_in[base + 1];
    const float* Wv      = (const float*)d_in[base + 2];
    const float* gamma   = (const float*)d_in[base + 3];
    const float* beta    = (const float*)d_in[base + 4];
    const float* prelu_a = (const float*)d_in[base + 5];
    const float* Wm      = (const float*)d_in[base + 6];
    const float* bm      = (const float*)d_in[base + 7];
    const float* Wnp     = (const float*)d_in[base + 8];
    const float* bnp     = (const float*)d_in[base + 9];
    const float* Wb_root = (const float*)d_in[base + 10];
    const float* Wb_msg  = (const float*)d_in[base + 11];
    const float* bb      = (const float*)d_in[base + 12];
    const float* Wf_root = (const float*)d_in[base + 13];
    const float* Wf_msg  = (const float*)d_in[base + 14];
    const float* bf      = (const float*)d_in[base + 15];
    const float* Wpb     = (const float*)d_in[base + 16];
    const float* bpb     = (const float*)d_in[base + 17];
    const float* Wpf     = (const float*)d_in[base + 18];
    const float* bpf     = (const float*)d_in[base + 19];

    k1_precompute<<<1, 512>>>(Wq, Wk, Wm, bm, Wnp, bnp,
                              Wb_root, Wb_msg, bb, Wf_root, Wf_msg, bf,
                              Wpb, bpb, Wpf, bpf);
    k2_attn<<<128, 256>>>(x);                                      // + zero counters
    k3_norm<16, true,  1><<<N_NODES / 8, 256>>>(vis_body, edge_b, edge_f, E); // + hist
    k_scanA<<<256, 256>>>();
    k_scanB<<<2, 128>>>();
    k_scanC<<<256, 256>>>();
    k3_norm<4,  false, 2><<<N_NODES / 8, 256>>>(vis_face, edge_b, edge_f, E); // + scatter
    k4_node<<<N_NODES / 256, 256>>>(Wv, gamma, beta, prelu_a);
    k5_sorted<VBDIM / 16, true,  false><<<N_NODES / 8, 256>>>(nullptr);
    k5_sorted<VFDIM / 16, false, true ><<<N_NODES / 8, 256>>>((float*)d_out); // + final combine
}